// round 2
// baseline (speedup 1.0000x reference)
#include <cuda_runtime.h>

#define RES 256
#define CELLS (RES*RES)
#define NCH 32
#define ACCSZ (CELLS*NCH)
#define NPLANE 3
#define NG 500000

// Scratch (device globals: allocation-free rule)
__device__ float  g_acc [NPLANE*ACCSZ];   // [plane][cell][ch]
__device__ float  g_cnt [NPLANE*CELLS];   // [plane][cell]
__device__ float  g_newT[NPLANE*ACCSZ];   // [plane][ch][cell]  (transposed, pre-LN)
__device__ double g_sum [NPLANE];
__device__ double g_ss  [NPLANE];
__device__ float  g_mu  [NPLANE];
__device__ float  g_inv [NPLANE];

// ---------------------------------------------------------------- zero
__global__ void k_zero() {
    int i = blockIdx.x * blockDim.x + threadIdx.x;
    int stride = gridDim.x * blockDim.x;
    for (int j = i; j < NPLANE*ACCSZ; j += stride) g_acc[j] = 0.f;
    for (int j = i; j < NPLANE*CELLS; j += stride) g_cnt[j] = 0.f;
    if (i < NPLANE) { g_sum[i] = 0.0; g_ss[i] = 0.0; }
}

// ---------------------------------------------------------------- scatter
// one warp per gaussian; lane = channel. 4 coalesced 128B RED lines per plane.
__global__ void k_scatter(const float* __restrict__ xyz,
                          const float* __restrict__ feats, int n) {
    int w    = (blockIdx.x * blockDim.x + threadIdx.x) >> 5;
    int lane = threadIdx.x & 31;
    if (w >= n) return;

    float gx = __ldg(xyz + 3*w + 0);
    float gy = __ldg(xyz + 3*w + 1);
    float gz = __ldg(xyz + 3*w + 2);
    float x = fminf(fmaxf((gx + 1.f) * 0.5f, 0.f), 0.999f) * (float)(RES - 1);
    float y = fminf(fmaxf((gy + 1.f) * 0.5f, 0.f), 0.999f) * (float)(RES - 1);
    float z = fminf(fmaxf((gz + 1.f) * 0.5f, 0.f), 0.999f) * (float)(RES - 1);

    #pragma unroll
    for (int p = 0; p < 3; p++) {
        float px = (p == 2) ? y : x;              // xy:(x,y) xz:(x,z) yz:(y,z)
        float py = (p == 0) ? y : z;

        int ix0 = (int)floorf(px);
        int iy0 = (int)floorf(py);
        int ix0c = min(max(ix0, 0), RES-1);
        int ix1c = min(ix0 + 1,    RES-1);
        int iy0c = min(max(iy0, 0), RES-1);
        int iy1c = min(iy0 + 1,    RES-1);

        float wx0 = fminf(fmaxf((float)ix1c - px, 0.f), 1.f);
        float wx1 = fminf(fmaxf(px - (float)ix0c, 0.f), 1.f);
        float wy0 = fminf(fmaxf((float)iy1c - py, 0.f), 1.f);
        float wy1 = fminf(fmaxf(py - (float)iy0c, 0.f), 1.f);

        // reference corner order: (y0,x0,wx0wy0) (y1,x0,wx0wy1) (y0,x1,wx1wy0) (y1,x1,wx1wy1)
        int l0 = iy0c*RES + ix0c;
        int l1 = iy1c*RES + ix0c;
        int l2 = iy0c*RES + ix1c;
        int l3 = iy1c*RES + ix1c;
        float w00 = wx0*wy0, w01 = wx0*wy1, w10 = wx1*wy0, w11 = wx1*wy1;

        float f = __ldg(feats + (size_t)w*96 + p*32 + lane);
        float* base = g_acc + (size_t)p*ACCSZ;
        atomicAdd(base + (size_t)l0*NCH + lane, f*w00);
        atomicAdd(base + (size_t)l1*NCH + lane, f*w01);
        atomicAdd(base + (size_t)l2*NCH + lane, f*w10);
        atomicAdd(base + (size_t)l3*NCH + lane, f*w11);

        if (lane < 4) {
            int ll = (lane == 0) ? l0 : (lane == 1) ? l1 : (lane == 2) ? l2 : l3;
            atomicAdd(g_cnt + p*CELLS + ll, 1.0f);
        }
    }
}

// ---------------------------------------------------------------- reduce + transpose
// thread per cell: divide by counts, write channel-major newT, accumulate sum/sumsq
__global__ void k_reduce() {
    int p    = blockIdx.y;
    int cell = blockIdx.x * blockDim.x + threadIdx.x;

    float cnt = g_cnt[p*CELLS + cell];
    float inv = 1.f / (cnt + 1e-6f);
    const float4* a = (const float4*)(g_acc + (size_t)p*ACCSZ + (size_t)cell*NCH);
    float* nt = g_newT + (size_t)p*ACCSZ;

    float s = 0.f, ss = 0.f;
    #pragma unroll
    for (int i = 0; i < 8; i++) {
        float4 v = a[i];
        float n0 = v.x*inv, n1 = v.y*inv, n2 = v.z*inv, n3 = v.w*inv;
        s  += n0 + n1 + n2 + n3;
        ss += n0*n0 + n1*n1 + n2*n2 + n3*n3;
        nt[(size_t)(i*4+0)*CELLS + cell] = n0;
        nt[(size_t)(i*4+1)*CELLS + cell] = n1;
        nt[(size_t)(i*4+2)*CELLS + cell] = n2;
        nt[(size_t)(i*4+3)*CELLS + cell] = n3;
    }

    double ds = (double)s, dss = (double)ss;
    #pragma unroll
    for (int off = 16; off; off >>= 1) {
        ds  += __shfl_down_sync(0xFFFFFFFFu, ds,  off);
        dss += __shfl_down_sync(0xFFFFFFFFu, dss, off);
    }
    __shared__ double shs[8], shss[8];
    int wid = threadIdx.x >> 5;
    if ((threadIdx.x & 31) == 0) { shs[wid] = ds; shss[wid] = dss; }
    __syncthreads();
    if (threadIdx.x == 0) {
        double t = 0.0, tt = 0.0;
        for (int i = 0; i < 8; i++) { t += shs[i]; tt += shss[i]; }
        atomicAdd(&g_sum[p], t);
        atomicAdd(&g_ss[p], tt);
    }
}

// ---------------------------------------------------------------- finalize stats
__global__ void k_finalize() {
    int p = threadIdx.x;
    if (p < NPLANE) {
        double n  = (double)ACCSZ;
        double mu = g_sum[p] / n;
        double var = g_ss[p] / n - mu * mu;
        g_mu[p]  = (float)mu;
        g_inv[p] = (float)(1.0 / sqrt(var + 1e-5));
    }
}

// ---------------------------------------------------------------- normalize + blur + residual
__global__ void k_blur(const float* __restrict__ p_xy,
                       const float* __restrict__ p_xz,
                       const float* __restrict__ p_yz,
                       const float* __restrict__ lnw,
                       const float* __restrict__ lnb,
                       float* __restrict__ out) {
    const float W0 = 0.054488684549642945f;
    const float W1 = 0.2442013422000340f;
    const float W2 = 0.4026199464998460f;

    int zc = blockIdx.z;
    int p = zc >> 5;
    int c = zc & 31;
    float mu  = g_mu[p];
    float inv = g_inv[p];

    const float* nt  = g_newT + (size_t)p*ACCSZ + (size_t)c*CELLS;
    const float* lw  = lnw + (size_t)c*CELLS;
    const float* lb  = lnb + (size_t)c*CELLS;

    __shared__ float raw[36][40];
    __shared__ float ht [36][32];

    int tid = threadIdx.y * 32 + threadIdx.x;
    int gx0 = blockIdx.x * 32 - 2;
    int gy0 = blockIdx.y * 32 - 2;

    for (int idx = tid; idx < 36*36; idx += 256) {
        int r  = idx / 36;
        int cc = idx - r*36;
        int gy = gy0 + r, gx = gx0 + cc;
        float v = 0.f;
        if ((unsigned)gy < (unsigned)RES && (unsigned)gx < (unsigned)RES) {
            int lin = gy*RES + gx;
            v = (nt[lin] - mu) * inv * lw[lin] + lb[lin];
        }
        raw[r][cc] = v;
    }
    __syncthreads();

    for (int idx = tid; idx < 36*32; idx += 256) {
        int r  = idx >> 5;
        int cc = idx & 31;
        ht[r][cc] = W0*(raw[r][cc]   + raw[r][cc+4])
                  + W1*(raw[r][cc+1] + raw[r][cc+3])
                  + W2* raw[r][cc+2];
    }
    __syncthreads();

    const float* plane = (p == 0) ? p_xy : (p == 1) ? p_xz : p_yz;
    int gx = blockIdx.x * 32 + threadIdx.x;
    #pragma unroll
    for (int k = 0; k < 4; k++) {
        int ty = threadIdx.y + k*8;
        int gy = blockIdx.y * 32 + ty;
        float o = W0*(ht[ty  ][threadIdx.x] + ht[ty+4][threadIdx.x])
                + W1*(ht[ty+1][threadIdx.x] + ht[ty+3][threadIdx.x])
                + W2* ht[ty+2][threadIdx.x];
        size_t off = (size_t)c*CELLS + (size_t)gy*RES + gx;
        out[(size_t)p*ACCSZ + off] = o + plane[off];
    }
}

// ---------------------------------------------------------------- launch
extern "C" void kernel_launch(void* const* d_in, const int* in_sizes, int n_in,
                              void* d_out, int out_size) {
    const float* plane_xy = (const float*)d_in[0];
    const float* plane_xz = (const float*)d_in[1];
    const float* plane_yz = (const float*)d_in[2];
    const float* ln_w     = (const float*)d_in[3];
    const float* ln_b     = (const float*)d_in[4];
    const float* feats    = (const float*)d_in[5];
    const float* xyz      = (const float*)d_in[6];
    float* out = (float*)d_out;
    int n = in_sizes[6] / 3;   // 500000

    k_zero<<<1024, 256>>>();
    {
        int threads = 256;
        int blocks  = (n * 32 + threads - 1) / threads;
        k_scatter<<<blocks, threads>>>(xyz, feats, n);
    }
    k_reduce<<<dim3(CELLS/256, NPLANE), 256>>>();
    k_finalize<<<1, 32>>>();
    k_blur<<<dim3(RES/32, RES/32, NPLANE*NCH), dim3(32, 8)>>>(
        plane_xy, plane_xz, plane_yz, ln_w, ln_b, out);
}